// round 1
// baseline (speedup 1.0000x reference)
#include <cuda_runtime.h>
#include <math.h>

#define BB   4
#define SSEQ 2048
#define DD   512
#define HH   8
#define DHH  64
#define E3   1536
#define NEGV -9000000000000000.0f

// Scratch (allocation-free rule: __device__ globals)
__device__ float g_q[BB*HH*SSEQ*DHH];    // [b,h,s,dh]
__device__ float g_k[BB*HH*SSEQ*DHH];
__device__ float g_v[BB*HH*SSEQ*DHH];
__device__ float g_attn[BB*SSEQ*DD];     // [b,s,d]

// ---------------------------------------------------------------------------
// Kernel 1: qkv[m,e] = sum_d x[m,d]*Wqkv[e,d] + b[e], scattered into
// g_q/g_k/g_v with [b,h,s,dh] layout. M=8192, N=1536, K=512.
// ---------------------------------------------------------------------------
__global__ __launch_bounds__(256) void qkv_gemm(const float* __restrict__ X,
                                                const float* __restrict__ W,
                                                const float* __restrict__ bias) {
    __shared__ float As[64][33];
    __shared__ float Bs[64][33];
    const int tid = threadIdx.x;
    const int ty = tid >> 4, tx = tid & 15;
    const int m0 = blockIdx.y << 6, n0 = blockIdx.x << 6;

    float acc[4][4] = {};

    for (int k0 = 0; k0 < DD; k0 += 32) {
        #pragma unroll
        for (int i = tid; i < 64*32; i += 256) {
            int r = i >> 5, c = i & 31;
            As[r][c] = X[(m0 + r)*DD + k0 + c];
            Bs[r][c] = W[(n0 + r)*DD + k0 + c];
        }
        __syncthreads();
        #pragma unroll
        for (int kk = 0; kk < 32; kk++) {
            float a[4], b[4];
            #pragma unroll
            for (int ii = 0; ii < 4; ii++) a[ii] = As[ty*4 + ii][kk];
            #pragma unroll
            for (int jj = 0; jj < 4; jj++) b[jj] = Bs[tx*4 + jj][kk];
            #pragma unroll
            for (int ii = 0; ii < 4; ii++)
                #pragma unroll
                for (int jj = 0; jj < 4; jj++)
                    acc[ii][jj] = fmaf(a[ii], b[jj], acc[ii][jj]);
        }
        __syncthreads();
    }

    #pragma unroll
    for (int ii = 0; ii < 4; ii++) {
        const int mg = m0 + ty*4 + ii;
        const int bI = mg >> 11;           // /SSEQ
        const int sI = mg & (SSEQ - 1);
        #pragma unroll
        for (int jj = 0; jj < 4; jj++) {
            const int e = n0 + tx*4 + jj;
            const float v = acc[ii][jj] + bias[e];
            const int h = e / 192;
            const int r = e - h*192;
            const int idx = ((bI*HH + h)*SSEQ + sI)*DHH + (r & 63);
            if (r < 64)       g_q[idx] = v;
            else if (r < 128) g_k[idx] = v;
            else              g_v[idx] = v;
        }
    }
}

// ---------------------------------------------------------------------------
// Kernel 2: flash attention per (b*h, q-tile of 64). Online softmax with
// key-mask. P buffer aliases the K tile SMEM (reloaded each key tile).
// ---------------------------------------------------------------------------
__global__ __launch_bounds__(256) void attn_kernel(const int* __restrict__ mask) {
    extern __shared__ float sm[];
    float* Qs  = sm;                 // [64][65]
    float* Ps  = Qs + 64*65;         // [64][65]: K tile, then logits/P
    float* Vs  = Ps + 64*65;         // [64][64]
    float* m_s = Vs + 64*64;         // [64] running max
    float* l_s = m_s + 64;           // [64] running sum
    float* a_s = l_s + 64;           // [64] alpha (rescale)
    float* mkf = a_s + 64;           // [64] mask flag (1 => masked)

    const int tid = threadIdx.x;
    const int ty = tid >> 4, tx = tid & 15;
    const int bh = blockIdx.x;
    const int bI = bh >> 3;
    const int h  = bh & 7;
    const int q0 = blockIdx.y << 6;

    // Load Q tile [64 rows][64 dh], padded stride 65
    const float* Qg = g_q + (size_t)(bh*SSEQ + q0)*DHH;
    for (int i = tid; i < 64*64; i += 256) {
        int r = i >> 6, c = i & 63;
        Qs[r*65 + c] = Qg[i];
    }
    if (tid < 64) { m_s[tid] = -INFINITY; l_s[tid] = 0.f; }

    float acc[4][4] = {};
    const float scale = 0.125f;   // 1/sqrt(64)

    for (int k0 = 0; k0 < SSEQ; k0 += 64) {
        const float* Kg = g_k + (size_t)(bh*SSEQ + k0)*DHH;
        const float* Vg = g_v + (size_t)(bh*SSEQ + k0)*DHH;
        for (int i = tid; i < 64*64; i += 256) {
            int r = i >> 6, c = i & 63;
            Ps[r*65 + c] = Kg[i];    // K tile, padded
            Vs[i]        = Vg[i];    // V tile, [k][dh] unpadded
        }
        if (tid < 64) mkf[tid] = (mask[bI*SSEQ + k0 + tid] == 0) ? 1.f : 0.f;
        __syncthreads();

        // logits S = Q K^T (4x4 per thread)
        float s[4][4] = {};
        #pragma unroll
        for (int kk = 0; kk < 64; kk++) {
            float a[4], b[4];
            #pragma unroll
            for (int ii = 0; ii < 4; ii++) a[ii] = Qs[(ty*4 + ii)*65 + kk];
            #pragma unroll
            for (int jj = 0; jj < 4; jj++) b[jj] = Ps[(tx*4 + jj)*65 + kk];
            #pragma unroll
            for (int ii = 0; ii < 4; ii++)
                #pragma unroll
                for (int jj = 0; jj < 4; jj++)
                    s[ii][jj] = fmaf(a[ii], b[jj], s[ii][jj]);
        }
        __syncthreads();  // K tile fully consumed; reuse Ps as logits buffer

        #pragma unroll
        for (int ii = 0; ii < 4; ii++)
            #pragma unroll
            for (int jj = 0; jj < 4; jj++) {
                const int j = tx*4 + jj;
                const float lg = (mkf[j] != 0.f) ? NEGV : s[ii][jj]*scale;
                Ps[(ty*4 + ii)*65 + j] = lg;
            }
        __syncthreads();

        // Online softmax: one thread per query row
        if (tid < 64) {
            float* row = Ps + tid*65;
            const float mo = m_s[tid];
            float mx = mo;
            #pragma unroll 8
            for (int j = 0; j < 64; j++) mx = fmaxf(mx, row[j]);
            const float al = __expf(mo - mx);       // expf(-inf)=0 on first tile
            float sum = 0.f;
            #pragma unroll 8
            for (int j = 0; j < 64; j++) {
                const float p = __expf(row[j] - mx);
                row[j] = p;
                sum += p;
            }
            m_s[tid] = mx;
            l_s[tid] = l_s[tid]*al + sum;
            a_s[tid] = al;
        }
        __syncthreads();

        // Rescale accumulator, then O += P @ V
        float al[4];
        #pragma unroll
        for (int ii = 0; ii < 4; ii++) al[ii] = a_s[ty*4 + ii];
        #pragma unroll
        for (int ii = 0; ii < 4; ii++)
            #pragma unroll
            for (int jj = 0; jj < 4; jj++)
                acc[ii][jj] *= al[ii];

        #pragma unroll
        for (int kk = 0; kk < 64; kk++) {
            float p[4];
            #pragma unroll
            for (int ii = 0; ii < 4; ii++) p[ii] = Ps[(ty*4 + ii)*65 + kk];
            const float4 v4 = *(const float4*)&Vs[kk*64 + tx*4];
            #pragma unroll
            for (int ii = 0; ii < 4; ii++) {
                acc[ii][0] = fmaf(p[ii], v4.x, acc[ii][0]);
                acc[ii][1] = fmaf(p[ii], v4.y, acc[ii][1]);
                acc[ii][2] = fmaf(p[ii], v4.z, acc[ii][2]);
                acc[ii][3] = fmaf(p[ii], v4.w, acc[ii][3]);
            }
        }
        __syncthreads();  // before next tile overwrites Ps/Vs
    }

    #pragma unroll
    for (int ii = 0; ii < 4; ii++) {
        const float inv = 1.f / l_s[ty*4 + ii];
        const int sI = q0 + ty*4 + ii;
        float* dst = g_attn + (size_t)(bI*SSEQ + sI)*DD + h*DHH + tx*4;
        #pragma unroll
        for (int jj = 0; jj < 4; jj++) dst[jj] = acc[ii][jj]*inv;
    }
}

// ---------------------------------------------------------------------------
// Kernel 3: out[m,e] = sum_d attn[m,d]*Wo[e,d] + bo[e]. M=8192, N=512, K=512.
// ---------------------------------------------------------------------------
__global__ __launch_bounds__(256) void out_gemm(const float* __restrict__ W,
                                                const float* __restrict__ bias,
                                                float* __restrict__ Out) {
    __shared__ float As[64][33];
    __shared__ float Bs[64][33];
    const int tid = threadIdx.x;
    const int ty = tid >> 4, tx = tid & 15;
    const int m0 = blockIdx.y << 6, n0 = blockIdx.x << 6;

    float acc[4][4] = {};

    for (int k0 = 0; k0 < DD; k0 += 32) {
        #pragma unroll
        for (int i = tid; i < 64*32; i += 256) {
            int r = i >> 5, c = i & 31;
            As[r][c] = g_attn[(size_t)(m0 + r)*DD + k0 + c];
            Bs[r][c] = W[(n0 + r)*DD + k0 + c];
        }
        __syncthreads();
        #pragma unroll
        for (int kk = 0; kk < 32; kk++) {
            float a[4], b[4];
            #pragma unroll
            for (int ii = 0; ii < 4; ii++) a[ii] = As[ty*4 + ii][kk];
            #pragma unroll
            for (int jj = 0; jj < 4; jj++) b[jj] = Bs[tx*4 + jj][kk];
            #pragma unroll
            for (int ii = 0; ii < 4; ii++)
                #pragma unroll
                for (int jj = 0; jj < 4; jj++)
                    acc[ii][jj] = fmaf(a[ii], b[jj], acc[ii][jj]);
        }
        __syncthreads();
    }

    #pragma unroll
    for (int ii = 0; ii < 4; ii++) {
        const int mg = m0 + ty*4 + ii;
        #pragma unroll
        for (int jj = 0; jj < 4; jj++) {
            const int e = n0 + tx*4 + jj;
            Out[(size_t)mg*DD + e] = acc[ii][jj] + bias[e];
        }
    }
}

// ---------------------------------------------------------------------------
extern "C" void kernel_launch(void* const* d_in, const int* in_sizes, int n_in,
                              void* d_out, int out_size) {
    const float* x    = (const float*)d_in[0];
    const int*   mask = (const int*)  d_in[1];
    const float* Wqkv = (const float*)d_in[2];
    const float* bqkv = (const float*)d_in[3];
    const float* Wo   = (const float*)d_in[4];
    const float* bo   = (const float*)d_in[5];
    float* out = (float*)d_out;

    const int attn_smem = (64*65*2 + 64*64 + 4*64) * (int)sizeof(float);  // 50688 B
    cudaFuncSetAttribute(attn_kernel, cudaFuncAttributeMaxDynamicSharedMemorySize,
                         attn_smem);

    qkv_gemm<<<dim3(E3/64, (BB*SSEQ)/64), 256>>>(x, Wqkv, bqkv);
    attn_kernel<<<dim3(BB*HH, SSEQ/64), 256, attn_smem>>>(mask);
    out_gemm<<<dim3(DD/64, (BB*SSEQ)/64), 256>>>(Wo, bo, out);
}

// round 3
// speedup vs baseline: 1.9188x; 1.9188x over previous
#include <cuda_runtime.h>
#include <math.h>
#include <stdint.h>

#define BB   4
#define SSEQ 2048
#define DD   512
#define HH   8
#define DHH  64
#define E3   1536
#define NEGV -9000000000000000.0f

// Scratch (allocation-free rule: __device__ globals)
__device__ float g_q[BB*HH*SSEQ*DHH];    // [b,h,s,dh]
__device__ float g_k[BB*HH*SSEQ*DHH];
__device__ float g_v[BB*HH*SSEQ*DHH];
__device__ float g_attn[BB*SSEQ*DD];     // [b,s,d]
__device__ int   g_cnt[BB];              // active-key count per batch
__device__ int   g_idx[BB*SSEQ];         // active key indices (unordered)

// ---------------------------------------------------------------------------
// TF32 mma.sync helpers (plain sm_80+ PTX — no sm_103a-only features)
// ---------------------------------------------------------------------------
__device__ __forceinline__ uint32_t f2tf32(float x) {
    uint32_t y;
    asm("cvt.rna.tf32.f32 %0, %1;" : "=r"(y) : "f"(x));
    return y;
}
__device__ __forceinline__ void mma_tf32(float (&d)[4], const uint32_t (&a)[4],
                                         const uint32_t (&b)[2]) {
    asm volatile("mma.sync.aligned.m16n8k8.row.col.f32.tf32.tf32.f32 "
                 "{%0,%1,%2,%3}, {%4,%5,%6,%7}, {%8,%9}, {%0,%1,%2,%3};"
                 : "+f"(d[0]), "+f"(d[1]), "+f"(d[2]), "+f"(d[3])
                 : "r"(a[0]), "r"(a[1]), "r"(a[2]), "r"(a[3]),
                   "r"(b[0]), "r"(b[1]));
}

// 128x128 CTA tile, 8 warps (2 along M x 4 along N), warp tile 64x32.
// Fragments per warp: 4 (M) x 4 (N) m16n8k8 accumulators.
// SMEM row stride 36 floats -> tf32 fragment loads are bank-conflict-free.
#define SMS 36

__device__ __forceinline__ void mma_mainloop(const float* __restrict__ Ag,
                                             const float* __restrict__ Bg,
                                             uint32_t* As, uint32_t* Ws,
                                             float acc[4][4][4]) {
    const int tid = threadIdx.x;
    const int wid = tid >> 5, lane = tid & 31;
    const int wm = wid >> 2, wn = wid & 3;
    const int lr = lane >> 2, lc = lane & 3;

    for (int kc = 0; kc < DD; kc += 32) {
        #pragma unroll
        for (int j = 0; j < 4; j++) {
            const int idx = tid + j * 256;
            const int r = idx >> 3, c4 = (idx & 7) * 4;
            const float4 va = *(const float4*)(Ag + (size_t)r * DD + kc + c4);
            const float4 vb = *(const float4*)(Bg + (size_t)r * DD + kc + c4);
            uint32_t* pa = As + r * SMS + c4;
            pa[0] = f2tf32(va.x); pa[1] = f2tf32(va.y);
            pa[2] = f2tf32(va.z); pa[3] = f2tf32(va.w);
            uint32_t* pb = Ws + r * SMS + c4;
            pb[0] = f2tf32(vb.x); pb[1] = f2tf32(vb.y);
            pb[2] = f2tf32(vb.z); pb[3] = f2tf32(vb.w);
        }
        __syncthreads();

        #pragma unroll
        for (int ks = 0; ks < 32; ks += 8) {
            uint32_t a[4][4], b[4][2];
            #pragma unroll
            for (int mf = 0; mf < 4; mf++) {
                const uint32_t* p = As + (wm*64 + mf*16 + lr) * SMS + ks + lc;
                a[mf][0] = p[0];
                a[mf][1] = p[8*SMS];
                a[mf][2] = p[4];
                a[mf][3] = p[8*SMS + 4];
            }
            #pragma unroll
            for (int nf = 0; nf < 4; nf++) {
                const uint32_t* p = Ws + (wn*32 + nf*8 + lr) * SMS + ks + lc;
                b[nf][0] = p[0];
                b[nf][1] = p[4];
            }
            #pragma unroll
            for (int mf = 0; mf < 4; mf++)
                #pragma unroll
                for (int nf = 0; nf < 4; nf++)
                    mma_tf32(acc[mf][nf], a[mf], b[nf]);
        }
        __syncthreads();
    }
}

// ---------------------------------------------------------------------------
// Kernel 1: QKV projection (tf32 mma.sync) + head-layout scatter
// grid: (1536/128, 8192/128)
// ---------------------------------------------------------------------------
__global__ __launch_bounds__(256) void qkv_mma(const float* __restrict__ X,
                                               const float* __restrict__ W,
                                               const float* __restrict__ bias) {
    __shared__ uint32_t As[128*SMS];
    __shared__ uint32_t Ws[128*SMS];
    const int m0 = blockIdx.y << 7, n0 = blockIdx.x << 7;
    float acc[4][4][4] = {};
    mma_mainloop(X + (size_t)m0 * DD, W + (size_t)n0 * DD, As, Ws, acc);

    const int tid = threadIdx.x;
    const int wid = tid >> 5, lane = tid & 31;
    const int wm = wid >> 2, wn = wid & 3;
    const int lr = lane >> 2, lc = lane & 3;

    #pragma unroll
    for (int mf = 0; mf < 4; mf++) {
        #pragma unroll
        for (int nf = 0; nf < 4; nf++) {
            const int cb = n0 + wn*32 + nf*8 + 2*lc;     // even
            const int h   = cb / 192;
            const int rr  = cb - h * 192;
            const int sel = rr >> 6;
            const int dh0 = rr & 63;
            float* gbase = (sel == 0 ? g_q : sel == 1 ? g_k : g_v);
            const float b0 = bias[cb], b1 = bias[cb + 1];
            #pragma unroll
            for (int half = 0; half < 2; half++) {
                const int row = m0 + wm*64 + mf*16 + lr + 8*half;
                const int bI = row >> 11, sI = row & (SSEQ - 1);
                float2 o;
                o.x = acc[mf][nf][2*half + 0] + b0;
                o.y = acc[mf][nf][2*half + 1] + b1;
                *(float2*)(gbase + ((size_t)(bI*HH + h)*SSEQ + sI)*DHH + dh0) = o;
            }
        }
    }
}

// ---------------------------------------------------------------------------
// Kernel 3: output projection (tf32 mma.sync). grid: (512/128, 8192/128)
// ---------------------------------------------------------------------------
__global__ __launch_bounds__(256) void out_mma(const float* __restrict__ W,
                                               const float* __restrict__ bias,
                                               float* __restrict__ Out) {
    __shared__ uint32_t As[128*SMS];
    __shared__ uint32_t Ws[128*SMS];
    const int m0 = blockIdx.y << 7, n0 = blockIdx.x << 7;
    float acc[4][4][4] = {};
    mma_mainloop(g_attn + (size_t)m0 * DD, W + (size_t)n0 * DD, As, Ws, acc);

    const int tid = threadIdx.x;
    const int wid = tid >> 5, lane = tid & 31;
    const int wm = wid >> 2, wn = wid & 3;
    const int lr = lane >> 2, lc = lane & 3;

    #pragma unroll
    for (int mf = 0; mf < 4; mf++) {
        #pragma unroll
        for (int nf = 0; nf < 4; nf++) {
            const int cb = n0 + wn*32 + nf*8 + 2*lc;
            const float b0 = bias[cb], b1 = bias[cb + 1];
            #pragma unroll
            for (int half = 0; half < 2; half++) {
                const int row = m0 + wm*64 + mf*16 + lr + 8*half;
                float2 o;
                o.x = acc[mf][nf][2*half + 0] + b0;
                o.y = acc[mf][nf][2*half + 1] + b1;
                *(float2*)(Out + (size_t)row * DD + cb) = o;
            }
        }
    }
}

// ---------------------------------------------------------------------------
// Mask compaction: unordered active-key index list per batch (softmax is
// order-invariant, and exp(NEG - max) == 0 exactly, so dropping masked keys
// is exact).
// ---------------------------------------------------------------------------
__global__ void zero_cnt() { if (threadIdx.x < BB) g_cnt[threadIdx.x] = 0; }
__global__ __launch_bounds__(256) void compact_mask(const int* __restrict__ mask) {
    const int t = blockIdx.x * 256 + threadIdx.x;
    const int b = t >> 11;
    if (mask[t] != 0) {
        const int p = atomicAdd(&g_cnt[b], 1);
        g_idx[b * SSEQ + p] = t & (SSEQ - 1);
    }
}

// ---------------------------------------------------------------------------
// Kernel 2: flash attention over compacted keys. grid: (B*H, S/64)
// ---------------------------------------------------------------------------
__global__ __launch_bounds__(256) void attn_kernel() {
    extern __shared__ float sm[];
    float* Qs  = sm;                 // [64][65]
    float* Ps  = Qs + 64*65;         // [64][65]: K tile, then logits/P
    float* Vs  = Ps + 64*65;         // [64][64]
    float* m_s = Vs + 64*64;         // [64] running max
    float* l_s = m_s + 64;           // [64] running sum
    float* a_s = l_s + 64;           // [64] alpha (rescale)

    const int tid = threadIdx.x;
    const int ty = tid >> 4, tx = tid & 15;
    const int bh = blockIdx.x;
    const int bI = bh >> 3;
    const int h  = bh & 7;
    const int q0 = blockIdx.y << 6;
    const int L  = g_cnt[bI];
    const int* idx = g_idx + bI * SSEQ;

    const float* Qg = g_q + (size_t)(bh * SSEQ + q0) * DHH;
    for (int i = tid; i < 64*64; i += 256) {
        int r = i >> 6, c = i & 63;
        Qs[r*65 + c] = Qg[i];
    }
    if (tid < 64) { m_s[tid] = -INFINITY; l_s[tid] = 0.f; }

    float acc[4][4] = {};
    const float scale = 0.125f;   // 1/sqrt(64)

    for (int k0 = 0; k0 < L; k0 += 64) {
        for (int i = tid; i < 64*64; i += 256) {
            const int r = i >> 6, c = i & 63;
            const int kr = (k0 + r < L) ? idx[k0 + r] : 0;
            const float* Kg = g_k + ((size_t)bh * SSEQ + kr) * DHH;
            const float* Vg = g_v + ((size_t)bh * SSEQ + kr) * DHH;
            Ps[r*65 + c] = Kg[c];
            Vs[i]        = Vg[c];
        }
        __syncthreads();

        // logits S = Q K^T (4x4 per thread)
        float s[4][4] = {};
        #pragma unroll
        for (int kk = 0; kk < 64; kk++) {
            float a[4], b[4];
            #pragma unroll
            for (int ii = 0; ii < 4; ii++) a[ii] = Qs[(ty*4 + ii)*65 + kk];
            #pragma unroll
            for (int jj = 0; jj < 4; jj++) b[jj] = Ps[(tx*4 + jj)*65 + kk];
            #pragma unroll
            for (int ii = 0; ii < 4; ii++)
                #pragma unroll
                for (int jj = 0; jj < 4; jj++)
                    s[ii][jj] = fmaf(a[ii], b[jj], s[ii][jj]);
        }
        __syncthreads();  // K tile consumed; reuse Ps for logits

        #pragma unroll
        for (int ii = 0; ii < 4; ii++)
            #pragma unroll
            for (int jj = 0; jj < 4; jj++) {
                const int j = tx*4 + jj;
                Ps[(ty*4 + ii)*65 + j] = (k0 + j < L) ? s[ii][jj]*scale : NEGV;
            }
        __syncthreads();

        // Online softmax: one thread per query row
        if (tid < 64) {
            float* row = Ps + tid*65;
            const float mo = m_s[tid];
            float mx = mo;
            #pragma unroll 8
            for (int j = 0; j < 64; j++) mx = fmaxf(mx, row[j]);
            const float al = __expf(mo - mx);
            float sum = 0.f;
            #pragma unroll 8
            for (int j = 0; j < 64; j++) {
                const float p = __expf(row[j] - mx);
                row[j] = p;
                sum += p;
            }
            m_s[tid] = mx;
            l_s[tid] = l_s[tid]*al + sum;
            a_s[tid] = al;
        }
        __syncthreads();

        float al[4];
        #pragma unroll
        for (int ii = 0; ii < 4; ii++) al[ii] = a_s[ty*4 + ii];
        #pragma unroll
        for (int ii = 0; ii < 4; ii++)
            #pragma unroll
            for (int jj = 0; jj < 4; jj++)
                acc[ii][jj] *= al[ii];

        #pragma unroll
        for (int kk = 0; kk < 64; kk++) {
            float p[4];
            #pragma unroll
            for (int ii = 0; ii < 4; ii++) p[ii] = Ps[(ty*4 + ii)*65 + kk];
            const float4 v4 = *(const float4*)&Vs[kk*64 + tx*4];
            #pragma unroll
            for (int ii = 0; ii < 4; ii++) {
                acc[ii][0] = fmaf(p[ii], v4.x, acc[ii][0]);
                acc[ii][1] = fmaf(p[ii], v4.y, acc[ii][1]);
                acc[ii][2] = fmaf(p[ii], v4.z, acc[ii][2]);
                acc[ii][3] = fmaf(p[ii], v4.w, acc[ii][3]);
            }
        }
        __syncthreads();
    }

    #pragma unroll
    for (int ii = 0; ii < 4; ii++) {
        const float inv = 1.f / l_s[ty*4 + ii];
        const int sI = q0 + ty*4 + ii;
        float* dst = g_attn + (size_t)(bI*SSEQ + sI)*DD + h*DHH + tx*4;
        #pragma unroll
        for (int jj = 0; jj < 4; jj++) dst[jj] = acc[ii][jj]*inv;
    }
}

// ---------------------------------------------------------------------------
extern "C" void kernel_launch(void* const* d_in, const int* in_sizes, int n_in,
                              void* d_out, int out_size) {
    const float* x    = (const float*)d_in[0];
    const int*   mask = (const int*)  d_in[1];
    const float* Wqkv = (const float*)d_in[2];
    const float* bqkv = (const float*)d_in[3];
    const float* Wo   = (const float*)d_in[4];
    const float* bo   = (const float*)d_in[5];
    float* out = (float*)d_out;

    const int attn_smem = (64*65*2 + 64*64 + 4*64) * (int)sizeof(float);
    cudaFuncSetAttribute(attn_kernel, cudaFuncAttributeMaxDynamicSharedMemorySize,
                         attn_smem);

    zero_cnt<<<1, 32>>>();
    compact_mask<<<(BB*SSEQ)/256, 256>>>(mask);
    qkv_mma<<<dim3(E3/128, (BB*SSEQ)/128), 256>>>(x, Wqkv, bqkv);
    attn_kernel<<<dim3(BB*HH, SSEQ/64), 256, attn_smem>>>();
    out_mma<<<dim3(DD/128, (BB*SSEQ)/128), 256>>>(Wo, bo, out);
}

// round 4
// speedup vs baseline: 4.0204x; 2.0953x over previous
#include <cuda_runtime.h>
#include <math.h>
#include <stdint.h>

#define BB   4
#define SSEQ 2048
#define DD   512
#define HH   8
#define DHH  64
#define E3   1536
#define NEGV -9000000000000000.0f

// Scratch (allocation-free rule: __device__ globals)
__device__ float g_q[BB*HH*SSEQ*DHH];    // [b,h,s,dh]
__device__ float g_k[BB*HH*SSEQ*DHH];
__device__ float g_v[BB*HH*SSEQ*DHH];
__device__ float g_attn[BB*SSEQ*DD];     // [b,s,d]
__device__ int   g_cnt[BB];              // active-key count per batch
__device__ int   g_idx[BB*SSEQ];         // active key indices (unordered)

// ---------------------------------------------------------------------------
// TF32 mma.sync helpers (plain sm_80+ PTX — no sm_103a-only features)
// ---------------------------------------------------------------------------
__device__ __forceinline__ uint32_t f2tf32(float x) {
    uint32_t y;
    asm("cvt.rna.tf32.f32 %0, %1;" : "=r"(y) : "f"(x));
    return y;
}
__device__ __forceinline__ void mma_tf32(float (&d)[4], const uint32_t (&a)[4],
                                         const uint32_t (&b)[2]) {
    asm volatile("mma.sync.aligned.m16n8k8.row.col.f32.tf32.tf32.f32 "
                 "{%0,%1,%2,%3}, {%4,%5,%6,%7}, {%8,%9}, {%0,%1,%2,%3};"
                 : "+f"(d[0]), "+f"(d[1]), "+f"(d[2]), "+f"(d[3])
                 : "r"(a[0]), "r"(a[1]), "r"(a[2]), "r"(a[3]),
                   "r"(b[0]), "r"(b[1]));
}

// Fast 2^x for x <= 0 on the FMA pipe (no MUFU). Magic-number round +
// degree-4 poly on [-0.5,0.5] + exponent insert. Rel err ~4e-5.
__device__ __forceinline__ float fexp2(float x) {
    x = fmaxf(x, -126.0f);
    const float z = x + 12582912.0f;                       // 1.5*2^23
    const int   n = (__float_as_int(z) & 0x7FFFFF) - 0x400000;
    const float f = x - (z - 12582912.0f);
    float p = fmaf(fmaf(fmaf(fmaf(0.00961813f, f, 0.05550411f),
                             f, 0.24022651f), f, 0.69314718f), f, 1.0f);
    return __int_as_float(__float_as_int(p) + (n << 23));
}

// ---------------------------------------------------------------------------
// Projection GEMMs: 128x128 CTA tile, 8 warps (2M x 4N), warp tile 64x32.
// SMEM row stride 36 -> conflict-free tf32 fragment loads.
// ---------------------------------------------------------------------------
#define SMS 36

__device__ __forceinline__ void mma_mainloop(const float* __restrict__ Ag,
                                             const float* __restrict__ Bg,
                                             uint32_t* As, uint32_t* Ws,
                                             float acc[4][4][4]) {
    const int tid = threadIdx.x;
    const int wid = tid >> 5, lane = tid & 31;
    const int wm = wid >> 2, wn = wid & 3;
    const int lr = lane >> 2, lc = lane & 3;

    for (int kc = 0; kc < DD; kc += 32) {
        #pragma unroll
        for (int j = 0; j < 4; j++) {
            const int idx = tid + j * 256;
            const int r = idx >> 3, c4 = (idx & 7) * 4;
            const float4 va = *(const float4*)(Ag + (size_t)r * DD + kc + c4);
            const float4 vb = *(const float4*)(Bg + (size_t)r * DD + kc + c4);
            uint32_t* pa = As + r * SMS + c4;
            pa[0] = f2tf32(va.x); pa[1] = f2tf32(va.y);
            pa[2] = f2tf32(va.z); pa[3] = f2tf32(va.w);
            uint32_t* pb = Ws + r * SMS + c4;
            pb[0] = f2tf32(vb.x); pb[1] = f2tf32(vb.y);
            pb[2] = f2tf32(vb.z); pb[3] = f2tf32(vb.w);
        }
        __syncthreads();

        #pragma unroll
        for (int ks = 0; ks < 32; ks += 8) {
            uint32_t a[4][4], b[4][2];
            #pragma unroll
            for (int mf = 0; mf < 4; mf++) {
                const uint32_t* p = As + (wm*64 + mf*16 + lr) * SMS + ks + lc;
                a[mf][0] = p[0];
                a[mf][1] = p[8*SMS];
                a[mf][2] = p[4];
                a[mf][3] = p[8*SMS + 4];
            }
            #pragma unroll
            for (int nf = 0; nf < 4; nf++) {
                const uint32_t* p = Ws + (wn*32 + nf*8 + lr) * SMS + ks + lc;
                b[nf][0] = p[0];
                b[nf][1] = p[4];
            }
            #pragma unroll
            for (int mf = 0; mf < 4; mf++)
                #pragma unroll
                for (int nf = 0; nf < 4; nf++)
                    mma_tf32(acc[mf][nf], a[mf], b[nf]);
        }
        __syncthreads();
    }
}

__global__ __launch_bounds__(256) void qkv_mma(const float* __restrict__ X,
                                               const float* __restrict__ W,
                                               const float* __restrict__ bias) {
    __shared__ uint32_t As[128*SMS];
    __shared__ uint32_t Ws[128*SMS];
    const int m0 = blockIdx.y << 7, n0 = blockIdx.x << 7;
    float acc[4][4][4] = {};
    mma_mainloop(X + (size_t)m0 * DD, W + (size_t)n0 * DD, As, Ws, acc);

    const int tid = threadIdx.x;
    const int wid = tid >> 5, lane = tid & 31;
    const int wm = wid >> 2, wn = wid & 3;
    const int lr = lane >> 2, lc = lane & 3;

    #pragma unroll
    for (int mf = 0; mf < 4; mf++) {
        #pragma unroll
        for (int nf = 0; nf < 4; nf++) {
            const int cb = n0 + wn*32 + nf*8 + 2*lc;     // even
            const int h   = cb / 192;
            const int rr  = cb - h * 192;
            const int sel = rr >> 6;
            const int dh0 = rr & 63;
            float* gbase = (sel == 0 ? g_q : sel == 1 ? g_k : g_v);
            const float b0 = bias[cb], b1 = bias[cb + 1];
            #pragma unroll
            for (int half = 0; half < 2; half++) {
                const int row = m0 + wm*64 + mf*16 + lr + 8*half;
                const int bI = row >> 11, sI = row & (SSEQ - 1);
                float2 o;
                o.x = acc[mf][nf][2*half + 0] + b0;
                o.y = acc[mf][nf][2*half + 1] + b1;
                *(float2*)(gbase + ((size_t)(bI*HH + h)*SSEQ + sI)*DHH + dh0) = o;
            }
        }
    }
}

__global__ __launch_bounds__(256) void out_mma(const float* __restrict__ W,
                                               const float* __restrict__ bias,
                                               float* __restrict__ Out) {
    __shared__ uint32_t As[128*SMS];
    __shared__ uint32_t Ws[128*SMS];
    const int m0 = blockIdx.y << 7, n0 = blockIdx.x << 7;
    float acc[4][4][4] = {};
    mma_mainloop(g_attn + (size_t)m0 * DD, W + (size_t)n0 * DD, As, Ws, acc);

    const int tid = threadIdx.x;
    const int wid = tid >> 5, lane = tid & 31;
    const int wm = wid >> 2, wn = wid & 3;
    const int lr = lane >> 2, lc = lane & 3;

    #pragma unroll
    for (int mf = 0; mf < 4; mf++) {
        #pragma unroll
        for (int nf = 0; nf < 4; nf++) {
            const int cb = n0 + wn*32 + nf*8 + 2*lc;
            const float b0 = bias[cb], b1 = bias[cb + 1];
            #pragma unroll
            for (int half = 0; half < 2; half++) {
                const int row = m0 + wm*64 + mf*16 + lr + 8*half;
                float2 o;
                o.x = acc[mf][nf][2*half + 0] + b0;
                o.y = acc[mf][nf][2*half + 1] + b1;
                *(float2*)(Out + (size_t)row * DD + cb) = o;
            }
        }
    }
}

// ---------------------------------------------------------------------------
// Mask compaction (exact: softmax is order-invariant; dropped keys would
// carry weight exp(NEG - max) == 0).
// ---------------------------------------------------------------------------
__global__ void zero_cnt() { if (threadIdx.x < BB) g_cnt[threadIdx.x] = 0; }
__global__ __launch_bounds__(256) void compact_mask(const int* __restrict__ mask) {
    const int t = blockIdx.x * 256 + threadIdx.x;
    const int b = t >> 11;
    if (mask[t] != 0) {
        const int p = atomicAdd(&g_cnt[b], 1);
        g_idx[b * SSEQ + p] = t & (SSEQ - 1);
    }
}

// ---------------------------------------------------------------------------
// Kernel 2: flash attention, tf32 mma.sync + FMA-pipe exp2 softmax.
// CTA = 128 q-rows x full key range; 8 warps, each 16 q-rows x 64-key tiles.
// grid: (B*H = 32, S/128 = 16)
// ---------------------------------------------------------------------------
#define QST 68   // Qs/Ps row stride (conflict-free fragment loads)
#define VST 66   // Vs row stride

__global__ __launch_bounds__(256, 2) void attn_mma() {
    extern __shared__ uint32_t smu[];
    uint32_t* Qs = smu;                  // [128][QST] tf32
    uint32_t* Ks = Qs + 128*QST;         // [64 keys][QST] tf32
    uint32_t* Vs = Ks + 64*QST;          // [64 dh][VST] tf32 (V transposed)
    uint32_t* Ps = Vs + 64*VST;          // [128][QST] tf32 attention weights

    const int tid = threadIdx.x;
    const int wid = tid >> 5, lane = tid & 31;
    const int lr = lane >> 2, lc = lane & 3;
    const int bh = blockIdx.x;
    const int bI = bh >> 3, h = bh & 7;
    const int q0 = blockIdx.y << 7;
    const int L  = g_cnt[bI];
    const int* idx = g_idx + bI * SSEQ;

    const float* Kbh = g_k + (size_t)bh * SSEQ * DHH;
    const float* Vbh = g_v + (size_t)bh * SSEQ * DHH;

    // Load Q tile (128 x 64) as tf32
    const float* Qg = g_q + ((size_t)bh * SSEQ + q0) * DHH;
    #pragma unroll
    for (int it = 0; it < 8; it++) {
        const int i = tid + it * 256;
        const int r = i >> 4, c4 = (i & 15) << 2;
        const float4 v = *(const float4*)(Qg + r * DHH + c4);
        uint32_t* p = Qs + r * QST + c4;
        p[0] = f2tf32(v.x); p[1] = f2tf32(v.y);
        p[2] = f2tf32(v.z); p[3] = f2tf32(v.w);
    }

    float o[8][4] = {};
    float m0r = -3.0e38f, m1r = -3.0e38f;
    float l0r = 0.f, l1r = 0.f;
    const float C = 0.18033688f;   // (1/sqrt(64)) * log2(e)

    const int qrow = (wid << 4) + lr;          // this lane's base q-row

    for (int k0 = 0; k0 < L; k0 += 64) {
        // Load K tile [key][dh] and V tile transposed [dh][key]
        #pragma unroll
        for (int it = 0; it < 4; it++) {
            const int i = tid + it * 256;
            const int r = i >> 4, c4 = (i & 15) << 2;
            const int rr = k0 + r;
            const int kr = idx[rr < L ? rr : L - 1];
            const float4 kv = *(const float4*)(Kbh + (size_t)kr * DHH + c4);
            uint32_t* pk = Ks + r * QST + c4;
            pk[0] = f2tf32(kv.x); pk[1] = f2tf32(kv.y);
            pk[2] = f2tf32(kv.z); pk[3] = f2tf32(kv.w);
            const float4 vv = *(const float4*)(Vbh + (size_t)kr * DHH + c4);
            Vs[(c4+0)*VST + r] = f2tf32(vv.x);
            Vs[(c4+1)*VST + r] = f2tf32(vv.y);
            Vs[(c4+2)*VST + r] = f2tf32(vv.z);
            Vs[(c4+3)*VST + r] = f2tf32(vv.w);
        }
        __syncthreads();

        // S = Q K^T  (per warp: 16 rows x 64 keys)
        float s[8][4] = {};
        #pragma unroll
        for (int ks = 0; ks < 8; ks++) {
            uint32_t a[4];
            const uint32_t* pa = Qs + qrow * QST + ks*8 + lc;
            a[0] = pa[0];
            a[1] = pa[8*QST];
            a[2] = pa[4];
            a[3] = pa[8*QST + 4];
            #pragma unroll
            for (int nf = 0; nf < 8; nf++) {
                uint32_t b[2];
                const uint32_t* pb = Ks + (nf*8 + lr) * QST + ks*8 + lc;
                b[0] = pb[0];
                b[1] = pb[4];
                mma_tf32(s[nf], a, b);
            }
        }

        // Scale + mask padding columns
        #pragma unroll
        for (int nf = 0; nf < 8; nf++) {
            const int cb = k0 + nf*8 + 2*lc;
            const bool v0 = cb < L, v1 = (cb + 1) < L;
            s[nf][0] = v0 ? s[nf][0]*C : -3.0e38f;
            s[nf][1] = v1 ? s[nf][1]*C : -3.0e38f;
            s[nf][2] = v0 ? s[nf][2]*C : -3.0e38f;
            s[nf][3] = v1 ? s[nf][3]*C : -3.0e38f;
        }

        // Row max (per-lane over nf, then across the 4 lanes of each row)
        float pm0 = -3.0e38f, pm1 = -3.0e38f;
        #pragma unroll
        for (int nf = 0; nf < 8; nf++) {
            pm0 = fmaxf(pm0, fmaxf(s[nf][0], s[nf][1]));
            pm1 = fmaxf(pm1, fmaxf(s[nf][2], s[nf][3]));
        }
        pm0 = fmaxf(pm0, __shfl_xor_sync(0xffffffffu, pm0, 1));
        pm0 = fmaxf(pm0, __shfl_xor_sync(0xffffffffu, pm0, 2));
        pm1 = fmaxf(pm1, __shfl_xor_sync(0xffffffffu, pm1, 1));
        pm1 = fmaxf(pm1, __shfl_xor_sync(0xffffffffu, pm1, 2));

        const float mn0 = fmaxf(m0r, pm0), mn1 = fmaxf(m1r, pm1);
        const float al0 = fexp2(m0r - mn0), al1 = fexp2(m1r - mn1);
        m0r = mn0; m1r = mn1;

        // exp2, write P (tf32) for the PV mma, accumulate row sums
        float sum0 = 0.f, sum1 = 0.f;
        uint32_t* Pw0 = Ps + qrow * QST + 2*lc;
        uint32_t* Pw1 = Pw0 + 8*QST;
        #pragma unroll
        for (int nf = 0; nf < 8; nf++) {
            const float p0 = fexp2(s[nf][0] - mn0);
            const float p1 = fexp2(s[nf][1] - mn0);
            const float p2 = fexp2(s[nf][2] - mn1);
            const float p3 = fexp2(s[nf][3] - mn1);
            sum0 += p0 + p1;
            sum1 += p2 + p3;
            Pw0[nf*8 + 0] = f2tf32(p0);
            Pw0[nf*8 + 1] = f2tf32(p1);
            Pw1[nf*8 + 0] = f2tf32(p2);
            Pw1[nf*8 + 1] = f2tf32(p3);
        }
        sum0 += __shfl_xor_sync(0xffffffffu, sum0, 1);
        sum0 += __shfl_xor_sync(0xffffffffu, sum0, 2);
        sum1 += __shfl_xor_sync(0xffffffffu, sum1, 1);
        sum1 += __shfl_xor_sync(0xffffffffu, sum1, 2);
        l0r = l0r * al0 + sum0;
        l1r = l1r * al1 + sum1;

        // Rescale O accumulator
        #pragma unroll
        for (int nf = 0; nf < 8; nf++) {
            o[nf][0] *= al0; o[nf][1] *= al0;
            o[nf][2] *= al1; o[nf][3] *= al1;
        }
        __syncwarp();   // P written by this warp, read by this warp's other lanes

        // O += P V   (A = P rows of this warp, B = V^T)
        #pragma unroll
        for (int ks = 0; ks < 8; ks++) {
            uint32_t a[4];
            const uint32_t* pa = Ps + qrow * QST + ks*8 + lc;
            a[0] = pa[0];
            a[1] = pa[8*QST];
            a[2] = pa[4];
            a[3] = pa[8*QST + 4];
            #pragma unroll
            for (int nf = 0; nf < 8; nf++) {
                uint32_t b[2];
                const uint32_t* pb = Vs + (nf*8 + lr) * VST + ks*8 + lc;
                b[0] = pb[0];
                b[1] = pb[4];
                mma_tf32(o[nf], a, b);
            }
        }
        __syncthreads();   // all warps done with Ks/Vs before next tile load
    }

    // Epilogue: normalize and write [b,s,d]
    const float inv0 = 1.f / l0r, inv1 = 1.f / l1r;
    const int s0 = q0 + qrow, s1 = s0 + 8;
    float* d0 = g_attn + ((size_t)bI * SSEQ + s0) * DD + h * DHH + 2*lc;
    float* d1 = g_attn + ((size_t)bI * SSEQ + s1) * DD + h * DHH + 2*lc;
    #pragma unroll
    for (int nf = 0; nf < 8; nf++) {
        float2 w0, w1;
        w0.x = o[nf][0] * inv0; w0.y = o[nf][1] * inv0;
        w1.x = o[nf][2] * inv1; w1.y = o[nf][3] * inv1;
        *(float2*)(d0 + nf*8) = w0;
        *(float2*)(d1 + nf*8) = w1;
    }
}

// ---------------------------------------------------------------------------
extern "C" void kernel_launch(void* const* d_in, const int* in_sizes, int n_in,
                              void* d_out, int out_size) {
    const float* x    = (const float*)d_in[0];
    const int*   mask = (const int*)  d_in[1];
    const float* Wqkv = (const float*)d_in[2];
    const float* bqkv = (const float*)d_in[3];
    const float* Wo   = (const float*)d_in[4];
    const float* bo   = (const float*)d_in[5];
    float* out = (float*)d_out;

    const int attn_smem = (128*QST + 64*QST + 64*VST + 128*QST) * (int)sizeof(uint32_t);
    cudaFuncSetAttribute(attn_mma, cudaFuncAttributeMaxDynamicSharedMemorySize,
                         attn_smem);

    zero_cnt<<<1, 32>>>();
    compact_mask<<<(BB*SSEQ)/256, 256>>>(mask);
    qkv_mma<<<dim3(E3/128, (BB*SSEQ)/128), 256>>>(x, Wqkv, bqkv);
    attn_mma<<<dim3(BB*HH, SSEQ/128), 256, attn_smem>>>();
    out_mma<<<dim3(DD/128, (BB*SSEQ)/128), 256>>>(Wo, bo, out);
}

// round 5
// speedup vs baseline: 4.3179x; 1.0740x over previous
#include <cuda_runtime.h>
#include <math.h>
#include <stdint.h>

#define BB   4
#define SSEQ 2048
#define DD   512
#define HH   8
#define DHH  64
#define E3   1536
#define NEGV -9000000000000000.0f

// Scratch (allocation-free rule: __device__ globals)
__device__ float g_q[BB*HH*SSEQ*DHH];    // [b,h,s,dh]
__device__ float g_k[BB*HH*SSEQ*DHH];
__device__ float g_v[BB*HH*SSEQ*DHH];
__device__ float g_attn[BB*SSEQ*DD];     // [b,s,d]
__device__ int   g_cnt[BB];              // active-key count per batch
__device__ int   g_idx[BB*SSEQ];         // active key indices (unordered)

// ---------------------------------------------------------------------------
// TF32 mma.sync helpers (plain sm_80+ PTX — no sm_103a-only features)
// ---------------------------------------------------------------------------
__device__ __forceinline__ uint32_t f2tf32(float x) {
    uint32_t y;
    asm("cvt.rna.tf32.f32 %0, %1;" : "=r"(y) : "f"(x));
    return y;
}
__device__ __forceinline__ void mma_tf32(float (&d)[4], const uint32_t (&a)[4],
                                         const uint32_t (&b)[2]) {
    asm volatile("mma.sync.aligned.m16n8k8.row.col.f32.tf32.tf32.f32 "
                 "{%0,%1,%2,%3}, {%4,%5,%6,%7}, {%8,%9}, {%0,%1,%2,%3};"
                 : "+f"(d[0]), "+f"(d[1]), "+f"(d[2]), "+f"(d[3])
                 : "r"(a[0]), "r"(a[1]), "r"(a[2]), "r"(a[3]),
                   "r"(b[0]), "r"(b[1]));
}

// Fast 2^x for x <= 0 on the FMA pipe (no MUFU). Rel err ~4e-5.
__device__ __forceinline__ float fexp2(float x) {
    x = fmaxf(x, -126.0f);
    const float z = x + 12582912.0f;                       // 1.5*2^23
    const int   n = (__float_as_int(z) & 0x7FFFFF) - 0x400000;
    const float f = x - (z - 12582912.0f);
    float p = fmaf(fmaf(fmaf(fmaf(0.00961813f, f, 0.05550411f),
                             f, 0.24022651f), f, 0.69314718f), f, 1.0f);
    return __int_as_float(__float_as_int(p) + (n << 23));
}

// ---------------------------------------------------------------------------
// Projection GEMMs: 128x128 CTA tile, 8 warps (2M x 4N), warp tile 64x32.
// ---------------------------------------------------------------------------
#define SMS 36

__device__ __forceinline__ void mma_mainloop(const float* __restrict__ Ag,
                                             const float* __restrict__ Bg,
                                             uint32_t* As, uint32_t* Ws,
                                             float acc[4][4][4]) {
    const int tid = threadIdx.x;
    const int wid = tid >> 5, lane = tid & 31;
    const int wm = wid >> 2, wn = wid & 3;
    const int lr = lane >> 2, lc = lane & 3;

    for (int kc = 0; kc < DD; kc += 32) {
        #pragma unroll
        for (int j = 0; j < 4; j++) {
            const int idx = tid + j * 256;
            const int r = idx >> 3, c4 = (idx & 7) * 4;
            const float4 va = *(const float4*)(Ag + (size_t)r * DD + kc + c4);
            const float4 vb = *(const float4*)(Bg + (size_t)r * DD + kc + c4);
            uint32_t* pa = As + r * SMS + c4;
            pa[0] = f2tf32(va.x); pa[1] = f2tf32(va.y);
            pa[2] = f2tf32(va.z); pa[3] = f2tf32(va.w);
            uint32_t* pb = Ws + r * SMS + c4;
            pb[0] = f2tf32(vb.x); pb[1] = f2tf32(vb.y);
            pb[2] = f2tf32(vb.z); pb[3] = f2tf32(vb.w);
        }
        __syncthreads();

        #pragma unroll
        for (int ks = 0; ks < 32; ks += 8) {
            uint32_t a[4][4], b[4][2];
            #pragma unroll
            for (int mf = 0; mf < 4; mf++) {
                const uint32_t* p = As + (wm*64 + mf*16 + lr) * SMS + ks + lc;
                a[mf][0] = p[0];
                a[mf][1] = p[8*SMS];
                a[mf][2] = p[4];
                a[mf][3] = p[8*SMS + 4];
            }
            #pragma unroll
            for (int nf = 0; nf < 4; nf++) {
                const uint32_t* p = Ws + (wn*32 + nf*8 + lr) * SMS + ks + lc;
                b[nf][0] = p[0];
                b[nf][1] = p[4];
            }
            #pragma unroll
            for (int mf = 0; mf < 4; mf++)
                #pragma unroll
                for (int nf = 0; nf < 4; nf++)
                    mma_tf32(acc[mf][nf], a[mf], b[nf]);
        }
        __syncthreads();
    }
}

__global__ __launch_bounds__(256) void qkv_mma(const float* __restrict__ X,
                                               const float* __restrict__ W,
                                               const float* __restrict__ bias) {
    __shared__ uint32_t As[128*SMS];
    __shared__ uint32_t Ws[128*SMS];
    const int m0 = blockIdx.y << 7, n0 = blockIdx.x << 7;
    float acc[4][4][4] = {};
    mma_mainloop(X + (size_t)m0 * DD, W + (size_t)n0 * DD, As, Ws, acc);

    const int tid = threadIdx.x;
    const int wid = tid >> 5, lane = tid & 31;
    const int wm = wid >> 2, wn = wid & 3;
    const int lr = lane >> 2, lc = lane & 3;

    #pragma unroll
    for (int mf = 0; mf < 4; mf++) {
        #pragma unroll
        for (int nf = 0; nf < 4; nf++) {
            const int cb = n0 + wn*32 + nf*8 + 2*lc;     // even
            const int h   = cb / 192;
            const int rr  = cb - h * 192;
            const int sel = rr >> 6;
            const int dh0 = rr & 63;
            float* gbase = (sel == 0 ? g_q : sel == 1 ? g_k : g_v);
            const float b0 = bias[cb], b1 = bias[cb + 1];
            #pragma unroll
            for (int half = 0; half < 2; half++) {
                const int row = m0 + wm*64 + mf*16 + lr + 8*half;
                const int bI = row >> 11, sI = row & (SSEQ - 1);
                float2 o;
                o.x = acc[mf][nf][2*half + 0] + b0;
                o.y = acc[mf][nf][2*half + 1] + b1;
                *(float2*)(gbase + ((size_t)(bI*HH + h)*SSEQ + sI)*DHH + dh0) = o;
            }
        }
    }
}

__global__ __launch_bounds__(256) void out_mma(const float* __restrict__ W,
                                               const float* __restrict__ bias,
                                               float* __restrict__ Out) {
    __shared__ uint32_t As[128*SMS];
    __shared__ uint32_t Ws[128*SMS];
    const int m0 = blockIdx.y << 7, n0 = blockIdx.x << 7;
    float acc[4][4][4] = {};
    mma_mainloop(g_attn + (size_t)m0 * DD, W + (size_t)n0 * DD, As, Ws, acc);

    const int tid = threadIdx.x;
    const int wid = tid >> 5, lane = tid & 31;
    const int wm = wid >> 2, wn = wid & 3;
    const int lr = lane >> 2, lc = lane & 3;

    #pragma unroll
    for (int mf = 0; mf < 4; mf++) {
        #pragma unroll
        for (int nf = 0; nf < 4; nf++) {
            const int cb = n0 + wn*32 + nf*8 + 2*lc;
            const float b0 = bias[cb], b1 = bias[cb + 1];
            #pragma unroll
            for (int half = 0; half < 2; half++) {
                const int row = m0 + wm*64 + mf*16 + lr + 8*half;
                float2 o;
                o.x = acc[mf][nf][2*half + 0] + b0;
                o.y = acc[mf][nf][2*half + 1] + b1;
                *(float2*)(Out + (size_t)row * DD + cb) = o;
            }
        }
    }
}

// ---------------------------------------------------------------------------
// Mask compaction (exact: softmax is order-invariant; dropped keys would
// carry weight exp(NEG - max) == 0).
// ---------------------------------------------------------------------------
__global__ void zero_cnt() { if (threadIdx.x < BB) g_cnt[threadIdx.x] = 0; }
__global__ __launch_bounds__(256) void compact_mask(const int* __restrict__ mask) {
    const int t = blockIdx.x * 256 + threadIdx.x;
    const int b = t >> 11;
    if (mask[t] != 0) {
        const int p = atomicAdd(&g_cnt[b], 1);
        g_idx[b * SSEQ + p] = t & (SSEQ - 1);
    }
}

// ---------------------------------------------------------------------------
// Kernel 2: flash attention, tf32 mma.sync, warp tile 32 q-rows x 64 keys.
// CTA = 8 warps = 256 q-rows. grid: (B*H = 32, S/256 = 8)
// ---------------------------------------------------------------------------
#define QST 68   // Qs/Ks/Ps row stride (conflict-free fragment loads)
#define VST 66   // Vs row stride

__global__ __launch_bounds__(256, 1) void attn_mma() {
    extern __shared__ uint32_t smu[];
    uint32_t* Qs = smu;                  // [256][QST] tf32
    uint32_t* Ks = Qs + 256*QST;         // [64 keys][QST] tf32
    uint32_t* Vs = Ks + 64*QST;          // [64 dh][VST] tf32 (V transposed)
    uint32_t* Ps = Vs + 64*VST;          // [256][QST] tf32 attention weights

    const int tid = threadIdx.x;
    const int wid = tid >> 5, lane = tid & 31;
    const int lr = lane >> 2, lc = lane & 3;
    const int bh = blockIdx.x;
    const int bI = bh >> 3, h = bh & 7;
    const int q0 = blockIdx.y << 8;
    const int L  = g_cnt[bI];
    const int* idx = g_idx + bI * SSEQ;

    const float* Kbh = g_k + (size_t)bh * SSEQ * DHH;
    const float* Vbh = g_v + (size_t)bh * SSEQ * DHH;

    // Load Q tile (256 x 64) as tf32, coalesced
    const float* Qg = g_q + ((size_t)bh * SSEQ + q0) * DHH;
    #pragma unroll
    for (int it = 0; it < 16; it++) {
        const int i = tid + it * 256;
        const int r = i >> 4, c4 = (i & 15) << 2;
        const float4 v = *(const float4*)(Qg + r * DHH + c4);
        uint32_t* p = Qs + r * QST + c4;
        p[0] = f2tf32(v.x); p[1] = f2tf32(v.y);
        p[2] = f2tf32(v.z); p[3] = f2tf32(v.w);
    }

    float o[2][8][4] = {};
    float mrow[2][2], lrow[2][2];
    mrow[0][0] = mrow[0][1] = mrow[1][0] = mrow[1][1] = -3.0e38f;
    lrow[0][0] = lrow[0][1] = lrow[1][0] = lrow[1][1] = 0.f;
    const float C = 0.18033688f;   // (1/sqrt(64)) * log2(e)

    const int base = wid << 5;     // warp's first q-row (32 rows per warp)

    for (int k0 = 0; k0 < L; k0 += 64) {
        // Load K tile [key][dh] and V tile transposed [dh][key]
        #pragma unroll
        for (int it = 0; it < 4; it++) {
            const int i = tid + it * 256;
            const int r = i >> 4, c4 = (i & 15) << 2;
            const int rr = k0 + r;
            const int kr = idx[rr < L ? rr : L - 1];
            const float4 kv = *(const float4*)(Kbh + (size_t)kr * DHH + c4);
            uint32_t* pk = Ks + r * QST + c4;
            pk[0] = f2tf32(kv.x); pk[1] = f2tf32(kv.y);
            pk[2] = f2tf32(kv.z); pk[3] = f2tf32(kv.w);
            const float4 vv = *(const float4*)(Vbh + (size_t)kr * DHH + c4);
            Vs[(c4+0)*VST + r] = f2tf32(vv.x);
            Vs[(c4+1)*VST + r] = f2tf32(vv.y);
            Vs[(c4+2)*VST + r] = f2tf32(vv.z);
            Vs[(c4+3)*VST + r] = f2tf32(vv.w);
        }
        __syncthreads();

        // S = Q K^T  (per warp: 32 rows x 64 keys; B frags shared by 2 row blocks)
        float s[2][8][4] = {};
        #pragma unroll
        for (int ks = 0; ks < 8; ks++) {
            uint32_t a[2][4];
            #pragma unroll
            for (int mf = 0; mf < 2; mf++) {
                const uint32_t* pa = Qs + (base + mf*16 + lr) * QST + ks*8 + lc;
                a[mf][0] = pa[0];
                a[mf][1] = pa[8*QST];
                a[mf][2] = pa[4];
                a[mf][3] = pa[8*QST + 4];
            }
            #pragma unroll
            for (int nf = 0; nf < 8; nf++) {
                uint32_t b[2];
                const uint32_t* pb = Ks + (nf*8 + lr) * QST + ks*8 + lc;
                b[0] = pb[0];
                b[1] = pb[4];
                mma_tf32(s[0][nf], a[0], b);
                mma_tf32(s[1][nf], a[1], b);
            }
        }

        // Scale + mask padding columns
        #pragma unroll
        for (int nf = 0; nf < 8; nf++) {
            const int cb = k0 + nf*8 + 2*lc;
            const bool v0 = cb < L, v1 = (cb + 1) < L;
            #pragma unroll
            for (int mf = 0; mf < 2; mf++) {
                s[mf][nf][0] = v0 ? s[mf][nf][0]*C : -3.0e38f;
                s[mf][nf][1] = v1 ? s[mf][nf][1]*C : -3.0e38f;
                s[mf][nf][2] = v0 ? s[mf][nf][2]*C : -3.0e38f;
                s[mf][nf][3] = v1 ? s[mf][nf][3]*C : -3.0e38f;
            }
        }

        // Online softmax per row block
        #pragma unroll
        for (int mf = 0; mf < 2; mf++) {
            float pm0 = -3.0e38f, pm1 = -3.0e38f;
            #pragma unroll
            for (int nf = 0; nf < 8; nf++) {
                pm0 = fmaxf(pm0, fmaxf(s[mf][nf][0], s[mf][nf][1]));
                pm1 = fmaxf(pm1, fmaxf(s[mf][nf][2], s[mf][nf][3]));
            }
            pm0 = fmaxf(pm0, __shfl_xor_sync(0xffffffffu, pm0, 1));
            pm0 = fmaxf(pm0, __shfl_xor_sync(0xffffffffu, pm0, 2));
            pm1 = fmaxf(pm1, __shfl_xor_sync(0xffffffffu, pm1, 1));
            pm1 = fmaxf(pm1, __shfl_xor_sync(0xffffffffu, pm1, 2));

            const float mn0 = fmaxf(mrow[mf][0], pm0);
            const float mn1 = fmaxf(mrow[mf][1], pm1);
            const float al0 = fexp2(mrow[mf][0] - mn0);
            const float al1 = fexp2(mrow[mf][1] - mn1);
            mrow[mf][0] = mn0; mrow[mf][1] = mn1;

            float sum0 = 0.f, sum1 = 0.f;
            uint32_t* Pw0 = Ps + (base + mf*16 + lr) * QST + 2*lc;
            uint32_t* Pw1 = Pw0 + 8*QST;
            #pragma unroll
            for (int nf = 0; nf < 8; nf++) {
                const float p0 = fexp2(s[mf][nf][0] - mn0);
                const float p1 = fexp2(s[mf][nf][1] - mn0);
                const float p2 = fexp2(s[mf][nf][2] - mn1);
                const float p3 = fexp2(s[mf][nf][3] - mn1);
                sum0 += p0 + p1;
                sum1 += p2 + p3;
                Pw0[nf*8 + 0] = f2tf32(p0);
                Pw0[nf*8 + 1] = f2tf32(p1);
                Pw1[nf*8 + 0] = f2tf32(p2);
                Pw1[nf*8 + 1] = f2tf32(p3);
            }
            sum0 += __shfl_xor_sync(0xffffffffu, sum0, 1);
            sum0 += __shfl_xor_sync(0xffffffffu, sum0, 2);
            sum1 += __shfl_xor_sync(0xffffffffu, sum1, 1);
            sum1 += __shfl_xor_sync(0xffffffffu, sum1, 2);
            lrow[mf][0] = lrow[mf][0] * al0 + sum0;
            lrow[mf][1] = lrow[mf][1] * al1 + sum1;

            #pragma unroll
            for (int nf = 0; nf < 8; nf++) {
                o[mf][nf][0] *= al0; o[mf][nf][1] *= al0;
                o[mf][nf][2] *= al1; o[mf][nf][3] *= al1;
            }
        }
        __syncwarp();   // P written by this warp, read by this warp's lanes

        // O += P V   (B frags shared by 2 row blocks)
        #pragma unroll
        for (int ks = 0; ks < 8; ks++) {
            uint32_t a[2][4];
            #pragma unroll
            for (int mf = 0; mf < 2; mf++) {
                const uint32_t* pa = Ps + (base + mf*16 + lr) * QST + ks*8 + lc;
                a[mf][0] = pa[0];
                a[mf][1] = pa[8*QST];
                a[mf][2] = pa[4];
                a[mf][3] = pa[8*QST + 4];
            }
            #pragma unroll
            for (int nf = 0; nf < 8; nf++) {
                uint32_t b[2];
                const uint32_t* pb = Vs + (nf*8 + lr) * VST + ks*8 + lc;
                b[0] = pb[0];
                b[1] = pb[4];
                mma_tf32(o[0][nf], a[0], b);
                mma_tf32(o[1][nf], a[1], b);
            }
        }
        __syncthreads();   // all warps done with Ks/Vs before next tile load
    }

    // Epilogue: normalize and write [b,s,d]
    #pragma unroll
    for (int mf = 0; mf < 2; mf++) {
        const float inv0 = 1.f / lrow[mf][0], inv1 = 1.f / lrow[mf][1];
        const int s0 = q0 + base + mf*16 + lr, s1 = s0 + 8;
        float* d0 = g_attn + ((size_t)bI * SSEQ + s0) * DD + h * DHH + 2*lc;
        float* d1 = g_attn + ((size_t)bI * SSEQ + s1) * DD + h * DHH + 2*lc;
        #pragma unroll
        for (int nf = 0; nf < 8; nf++) {
            float2 w0, w1;
            w0.x = o[mf][nf][0] * inv0; w0.y = o[mf][nf][1] * inv0;
            w1.x = o[mf][nf][2] * inv1; w1.y = o[mf][nf][3] * inv1;
            *(float2*)(d0 + nf*8) = w0;
            *(float2*)(d1 + nf*8) = w1;
        }
    }
}

// ---------------------------------------------------------------------------
extern "C" void kernel_launch(void* const* d_in, const int* in_sizes, int n_in,
                              void* d_out, int out_size) {
    const float* x    = (const float*)d_in[0];
    const int*   mask = (const int*)  d_in[1];
    const float* Wqkv = (const float*)d_in[2];
    const float* bqkv = (const float*)d_in[3];
    const float* Wo   = (const float*)d_in[4];
    const float* bo   = (const float*)d_in[5];
    float* out = (float*)d_out;

    const int attn_smem = (256*QST + 64*QST + 64*VST + 256*QST) * (int)sizeof(uint32_t);
    cudaFuncSetAttribute(attn_mma, cudaFuncAttributeMaxDynamicSharedMemorySize,
                         attn_smem);

    zero_cnt<<<1, 32>>>();
    compact_mask<<<(BB*SSEQ)/256, 256>>>(mask);
    qkv_mma<<<dim3(E3/128, (BB*SSEQ)/128), 256>>>(x, Wqkv, bqkv);
    attn_mma<<<dim3(BB*HH, SSEQ/256), 256, attn_smem>>>();
    out_mma<<<dim3(DD/128, (BB*SSEQ)/128), 256>>>(Wo, bo, out);
}

// round 7
// speedup vs baseline: 4.6568x; 1.0785x over previous
#include <cuda_runtime.h>
#include <math.h>
#include <stdint.h>

#define BB   4
#define SSEQ 2048
#define DD   512
#define HH   8
#define DHH  64
#define E3   1536

// Scratch (allocation-free rule: __device__ globals)
__device__ float g_q[BB*HH*SSEQ*DHH];    // [b,h,s,dh]
__device__ float g_k[BB*HH*SSEQ*DHH];
__device__ float g_v[BB*HH*SSEQ*DHH];
__device__ float g_attn[BB*SSEQ*DD];     // [b,s,d]
__device__ int   g_cnt[BB];              // active-key count per batch
__device__ int   g_idx[BB*SSEQ];         // active key indices (unordered)

// ---------------------------------------------------------------------------
// TF32 mma.sync helpers (plain sm_80+ PTX)
// ---------------------------------------------------------------------------
__device__ __forceinline__ uint32_t f2tf32(float x) {
    uint32_t y;
    asm("cvt.rna.tf32.f32 %0, %1;" : "=r"(y) : "f"(x));
    return y;
}
__device__ __forceinline__ void mma_tf32(float (&d)[4], const uint32_t (&a)[4],
                                         const uint32_t (&b)[2]) {
    asm volatile("mma.sync.aligned.m16n8k8.row.col.f32.tf32.tf32.f32 "
                 "{%0,%1,%2,%3}, {%4,%5,%6,%7}, {%8,%9}, {%0,%1,%2,%3};"
                 : "+f"(d[0]), "+f"(d[1]), "+f"(d[2]), "+f"(d[3])
                 : "r"(a[0]), "r"(a[1]), "r"(a[2]), "r"(a[3]),
                   "r"(b[0]), "r"(b[1]));
}
__device__ __forceinline__ uint32_t smem_u32(const void* p) {
    uint32_t a;
    asm("{ .reg .u64 t; cvta.to.shared.u64 t, %1; cvt.u32.u64 %0, t; }"
        : "=r"(a) : "l"(p));
    return a;
}

// Fast 2^x for x <= 0 on the FMA pipe (no MUFU). Rel err ~4e-5.
__device__ __forceinline__ float fexp2(float x) {
    x = fmaxf(x, -126.0f);
    const float z = x + 12582912.0f;                       // 1.5*2^23
    const int   n = (__float_as_int(z) & 0x7FFFFF) - 0x400000;
    const float f = x - (z - 12582912.0f);
    float p = fmaf(fmaf(fmaf(fmaf(0.00961813f, f, 0.05550411f),
                             f, 0.24022651f), f, 0.69314718f), f, 1.0f);
    return __int_as_float(__float_as_int(p) + (n << 23));
}

// ---------------------------------------------------------------------------
// Projection GEMMs: 128x128 CTA tile, 8 warps (2M x 4N), warp tile 64x32.
// ---------------------------------------------------------------------------
#define SMS 36

__device__ __forceinline__ void mma_mainloop(const float* __restrict__ Ag,
                                             const float* __restrict__ Bg,
                                             uint32_t* As, uint32_t* Ws,
                                             float acc[4][4][4]) {
    const int tid = threadIdx.x;
    const int wid = tid >> 5, lane = tid & 31;
    const int wm = wid >> 2, wn = wid & 3;
    const int lr = lane >> 2, lc = lane & 3;

    for (int kc = 0; kc < DD; kc += 32) {
        #pragma unroll
        for (int j = 0; j < 4; j++) {
            const int idx = tid + j * 256;
            const int r = idx >> 3, c4 = (idx & 7) * 4;
            const float4 va = *(const float4*)(Ag + (size_t)r * DD + kc + c4);
            const float4 vb = *(const float4*)(Bg + (size_t)r * DD + kc + c4);
            uint32_t* pa = As + r * SMS + c4;
            pa[0] = f2tf32(va.x); pa[1] = f2tf32(va.y);
            pa[2] = f2tf32(va.z); pa[3] = f2tf32(va.w);
            uint32_t* pb = Ws + r * SMS + c4;
            pb[0] = f2tf32(vb.x); pb[1] = f2tf32(vb.y);
            pb[2] = f2tf32(vb.z); pb[3] = f2tf32(vb.w);
        }
        __syncthreads();

        #pragma unroll
        for (int ks = 0; ks < 32; ks += 8) {
            uint32_t a[4][4], b[4][2];
            #pragma unroll
            for (int mf = 0; mf < 4; mf++) {
                const uint32_t* p = As + (wm*64 + mf*16 + lr) * SMS + ks + lc;
                a[mf][0] = p[0];
                a[mf][1] = p[8*SMS];
                a[mf][2] = p[4];
                a[mf][3] = p[8*SMS + 4];
            }
            #pragma unroll
            for (int nf = 0; nf < 4; nf++) {
                const uint32_t* p = Ws + (wn*32 + nf*8 + lr) * SMS + ks + lc;
                b[nf][0] = p[0];
                b[nf][1] = p[4];
            }
            #pragma unroll
            for (int mf = 0; mf < 4; mf++)
                #pragma unroll
                for (int nf = 0; nf < 4; nf++)
                    mma_tf32(acc[mf][nf], a[mf], b[nf]);
        }
        __syncthreads();
    }
}

__global__ __launch_bounds__(256) void qkv_mma(const float* __restrict__ X,
                                               const float* __restrict__ W,
                                               const float* __restrict__ bias) {
    __shared__ uint32_t As[128*SMS];
    __shared__ uint32_t Ws[128*SMS];
    const int m0 = blockIdx.y << 7, n0 = blockIdx.x << 7;
    float acc[4][4][4] = {};
    mma_mainloop(X + (size_t)m0 * DD, W + (size_t)n0 * DD, As, Ws, acc);

    const int tid = threadIdx.x;
    const int wid = tid >> 5, lane = tid & 31;
    const int wm = wid >> 2, wn = wid & 3;
    const int lr = lane >> 2, lc = lane & 3;

    #pragma unroll
    for (int mf = 0; mf < 4; mf++) {
        #pragma unroll
        for (int nf = 0; nf < 4; nf++) {
            const int cb = n0 + wn*32 + nf*8 + 2*lc;     // even
            const int h   = cb / 192;
            const int rr  = cb - h * 192;
            const int sel = rr >> 6;
            const int dh0 = rr & 63;
            float* gbase = (sel == 0 ? g_q : sel == 1 ? g_k : g_v);
            const float b0 = bias[cb], b1 = bias[cb + 1];
            #pragma unroll
            for (int half = 0; half < 2; half++) {
                const int row = m0 + wm*64 + mf*16 + lr + 8*half;
                const int bI = row >> 11, sI = row & (SSEQ - 1);
                float2 o;
                o.x = acc[mf][nf][2*half + 0] + b0;
                o.y = acc[mf][nf][2*half + 1] + b1;
                *(float2*)(gbase + ((size_t)(bI*HH + h)*SSEQ + sI)*DHH + dh0) = o;
            }
        }
    }
}

__global__ __launch_bounds__(256) void out_mma(const float* __restrict__ W,
                                               const float* __restrict__ bias,
                                               float* __restrict__ Out) {
    __shared__ uint32_t As[128*SMS];
    __shared__ uint32_t Ws[128*SMS];
    const int m0 = blockIdx.y << 7, n0 = blockIdx.x << 7;
    float acc[4][4][4] = {};
    mma_mainloop(g_attn + (size_t)m0 * DD, W + (size_t)n0 * DD, As, Ws, acc);

    const int tid = threadIdx.x;
    const int wid = tid >> 5, lane = tid & 31;
    const int wm = wid >> 2, wn = wid & 3;
    const int lr = lane >> 2, lc = lane & 3;

    #pragma unroll
    for (int mf = 0; mf < 4; mf++) {
        #pragma unroll
        for (int nf = 0; nf < 4; nf++) {
            const int cb = n0 + wn*32 + nf*8 + 2*lc;
            const float b0 = bias[cb], b1 = bias[cb + 1];
            #pragma unroll
            for (int half = 0; half < 2; half++) {
                const int row = m0 + wm*64 + mf*16 + lr + 8*half;
                float2 o;
                o.x = acc[mf][nf][2*half + 0] + b0;
                o.y = acc[mf][nf][2*half + 1] + b1;
                *(float2*)(Out + (size_t)row * DD + cb) = o;
            }
        }
    }
}

// ---------------------------------------------------------------------------
// Mask compaction, single launch (exact: softmax order-invariant; dropped
// keys would carry weight exp(NEG - max) == 0).
// ---------------------------------------------------------------------------
__global__ __launch_bounds__(1024) void compact_one(const int* __restrict__ mask) {
    const int tid = threadIdx.x;
    if (tid < BB) g_cnt[tid] = 0;
    __syncthreads();
    #pragma unroll
    for (int i = tid; i < BB*SSEQ; i += 1024) {
        if (mask[i] != 0) {
            const int b = i >> 11;
            const int p = atomicAdd(&g_cnt[b], 1);
            g_idx[b * SSEQ + p] = i & (SSEQ - 1);
        }
    }
}

// ---------------------------------------------------------------------------
// Kernel 2: flash attention, tf32 mma.sync, warp tile 32 q-rows x 64 keys,
// cp.async double-buffered K/V pipeline. CTA = 8 warps = 256 q-rows.
// grid: (B*H = 32, S/256 = 8)
// ---------------------------------------------------------------------------
#define QST 68   // Qs/Ps row stride (conflict-free fragment access)
#define KST 68   // Ks row stride [key][dh]
#define VST 72   // Vs row stride [key][dh]; 72%32=8 -> conflict-free B frags

// Full-tile cp.async prefetch: 64 rows x 256 B each for K and V.
// 256 threads x 4 iters x 16 B covers one tensor tile exactly.
__device__ __forceinline__ void prefetch_tile(const float* Kbh, const float* Vbh,
                                              const int* idx, int t, int L,
                                              uint32_t ks_byte, uint32_t vs_byte,
                                              int tid) {
    const uint32_t bo = (uint32_t)((t & 1) * 64);
    #pragma unroll
    for (int it = 0; it < 4; it++) {
        const int i = tid + it * 256;
        const int r = i >> 4;               // key row 0..63
        const int ch = (i & 15) * 16;       // byte chunk within 256B row
        const int rr = (t << 6) + r;
        const int kr = idx[rr < L ? rr : L - 1];
        const void* gk = (const char*)(Kbh + (size_t)kr * DHH) + ch;
        const void* gv = (const char*)(Vbh + (size_t)kr * DHH) + ch;
        const uint32_t dk = ks_byte + (bo + (uint32_t)r) * (KST*4) + ch;
        const uint32_t dv = vs_byte + (bo + (uint32_t)r) * (VST*4) + ch;
        asm volatile("cp.async.cg.shared.global [%0], [%1], 16;" :: "r"(dk), "l"(gk));
        asm volatile("cp.async.cg.shared.global [%0], [%1], 16;" :: "r"(dv), "l"(gv));
    }
    asm volatile("cp.async.commit_group;" ::: "memory");
}

__global__ __launch_bounds__(256) void attn_mma() {
    extern __shared__ uint32_t smu[];
    uint32_t* Qs  = smu;                     // [256][QST] tf32
    uint32_t* Ps  = smu + 256*QST;           // [256][QST] tf32 weights
    uint32_t* KsB = smu + 512*QST;           // [2][64][KST] fp32 (raw)
    uint32_t* VsB = KsB + 2*64*KST;          // [2][64][VST] fp32 (raw)
    const uint32_t sb = smem_u32(smu);
    const uint32_t ks_byte = sb + 512*QST*4;
    const uint32_t vs_byte = ks_byte + 2*64*KST*4;

    const int tid = threadIdx.x;
    const int wid = tid >> 5, lane = tid & 31;
    const int lr = lane >> 2, lc = lane & 3;
    const int bh = blockIdx.x;
    const int bI = bh >> 3, h = bh & 7;
    const int q0 = blockIdx.y << 8;
    const int L  = g_cnt[bI];
    const int* idx = g_idx + bI * SSEQ;
    const float* Kbh = g_k + (size_t)bh * SSEQ * DHH;
    const float* Vbh = g_v + (size_t)bh * SSEQ * DHH;
    const int nT = (L + 63) >> 6;

    // Prefetch tile 0
    prefetch_tile(Kbh, Vbh, idx, 0, L, ks_byte, vs_byte, tid);

    // Load Q tile (256 x 64) as tf32 (overlaps with cp.async flight)
    const float* Qg = g_q + ((size_t)bh * SSEQ + q0) * DHH;
    #pragma unroll
    for (int it = 0; it < 16; it++) {
        const int i = tid + it * 256;
        const int r = i >> 4, c4 = (i & 15) << 2;
        const float4 v = *(const float4*)(Qg + r * DHH + c4);
        uint32_t* p = Qs + r * QST + c4;
        p[0] = f2tf32(v.x); p[1] = f2tf32(v.y);
        p[2] = f2tf32(v.z); p[3] = f2tf32(v.w);
    }

    float o[2][8][4] = {};
    float mrow[2][2], lrow[2][2];
    mrow[0][0] = mrow[0][1] = mrow[1][0] = mrow[1][1] = -3.0e38f;
    lrow[0][0] = lrow[0][1] = lrow[1][0] = lrow[1][1] = 0.f;
    const float C = 0.18033688f;   // (1/sqrt(64)) * log2(e)
    const int base = wid << 5;     // warp's first q-row (32 rows per warp)

    for (int t = 0; t < nT; t++) {
        // Prefetch tile t+1 (clamped; buffer (t+1)&1 was drained at end of t-1)
        prefetch_tile(Kbh, Vbh, idx, (t + 1 < nT) ? t + 1 : nT - 1, L,
                      ks_byte, vs_byte, tid);
        asm volatile("cp.async.wait_group 1;" ::: "memory");   // tile t landed
        __syncthreads();

        const uint32_t* Kc = KsB + (t & 1) * 64 * KST;
        const uint32_t* Vc = VsB + (t & 1) * 64 * VST;
        const int k0 = t << 6;

        // S = Q K^T  (per warp: 32 rows x 64 keys; B frags shared by 2 blocks)
        float s[2][8][4] = {};
        #pragma unroll
        for (int ks = 0; ks < 8; ks++) {
            uint32_t a[2][4];
            #pragma unroll
            for (int mf = 0; mf < 2; mf++) {
                const uint32_t* pa = Qs + (base + mf*16 + lr) * QST + ks*8 + lc;
                a[mf][0] = pa[0];
                a[mf][1] = pa[8*QST];
                a[mf][2] = pa[4];
                a[mf][3] = pa[8*QST + 4];
            }
            #pragma unroll
            for (int nf = 0; nf < 8; nf++) {
                uint32_t b[2];
                const uint32_t* pb = Kc + (nf*8 + lr) * KST + ks*8 + lc;
                b[0] = pb[0];
                b[1] = pb[4];
                mma_tf32(s[0][nf], a[0], b);
                mma_tf32(s[1][nf], a[1], b);
            }
        }

        // Scale + mask padding columns
        #pragma unroll
        for (int nf = 0; nf < 8; nf++) {
            const int cb = k0 + nf*8 + 2*lc;
            const bool v0 = cb < L, v1 = (cb + 1) < L;
            #pragma unroll
            for (int mf = 0; mf < 2; mf++) {
                s[mf][nf][0] = v0 ? s[mf][nf][0]*C : -3.0e38f;
                s[mf][nf][1] = v1 ? s[mf][nf][1]*C : -3.0e38f;
                s[mf][nf][2] = v0 ? s[mf][nf][2]*C : -3.0e38f;
                s[mf][nf][3] = v1 ? s[mf][nf][3]*C : -3.0e38f;
            }
        }

        // Online softmax per row block
        #pragma unroll
        for (int mf = 0; mf < 2; mf++) {
            float pm0 = -3.0e38f, pm1 = -3.0e38f;
            #pragma unroll
            for (int nf = 0; nf < 8; nf++) {
                pm0 = fmaxf(pm0, fmaxf(s[mf][nf][0], s[mf][nf][1]));
                pm1 = fmaxf(pm1, fmaxf(s[mf][nf][2], s[mf][nf][3]));
            }
            pm0 = fmaxf(pm0, __shfl_xor_sync(0xffffffffu, pm0, 1));
            pm0 = fmaxf(pm0, __shfl_xor_sync(0xffffffffu, pm0, 2));
            pm1 = fmaxf(pm1, __shfl_xor_sync(0xffffffffu, pm1, 1));
            pm1 = fmaxf(pm1, __shfl_xor_sync(0xffffffffu, pm1, 2));

            const float mn0 = fmaxf(mrow[mf][0], pm0);
            const float mn1 = fmaxf(mrow[mf][1], pm1);
            const float al0 = fexp2(mrow[mf][0] - mn0);
            const float al1 = fexp2(mrow[mf][1] - mn1);
            mrow[mf][0] = mn0; mrow[mf][1] = mn1;

            float sum0 = 0.f, sum1 = 0.f;
            uint32_t* Pw0 = Ps + (base + mf*16 + lr) * QST + 2*lc;
            uint32_t* Pw1 = Pw0 + 8*QST;
            #pragma unroll
            for (int nf = 0; nf < 8; nf++) {
                const float p0 = fexp2(s[mf][nf][0] - mn0);
                const float p1 = fexp2(s[mf][nf][1] - mn0);
                const float p2 = fexp2(s[mf][nf][2] - mn1);
                const float p3 = fexp2(s[mf][nf][3] - mn1);
                sum0 += p0 + p1;
                sum1 += p2 + p3;
                Pw0[nf*8 + 0] = f2tf32(p0);
                Pw0[nf*8 + 1] = f2tf32(p1);
                Pw1[nf*8 + 0] = f2tf32(p2);
                Pw1[nf*8 + 1] = f2tf32(p3);
            }
            sum0 += __shfl_xor_sync(0xffffffffu, sum0, 1);
            sum0 += __shfl_xor_sync(0xffffffffu, sum0, 2);
            sum1 += __shfl_xor_sync(0xffffffffu, sum1, 1);
            sum1 += __shfl_xor_sync(0xffffffffu, sum1, 2);
            lrow[mf][0] = lrow[mf][0] * al0 + sum0;
            lrow[mf][1] = lrow[mf][1] * al1 + sum1;

            #pragma unroll
            for (int nf = 0; nf < 8; nf++) {
                o[mf][nf][0] *= al0; o[mf][nf][1] *= al0;
                o[mf][nf][2] *= al1; o[mf][nf][3] *= al1;
            }
        }
        __syncwarp();   // P written by this warp, read by this warp's lanes

        // O += P V   (B frags from Vc[key][dh], shared by 2 row blocks)
        #pragma unroll
        for (int ks = 0; ks < 8; ks++) {
            uint32_t a[2][4];
            #pragma unroll
            for (int mf = 0; mf < 2; mf++) {
                const uint32_t* pa = Ps + (base + mf*16 + lr) * QST + ks*8 + lc;
                a[mf][0] = pa[0];
                a[mf][1] = pa[8*QST];
                a[mf][2] = pa[4];
                a[mf][3] = pa[8*QST + 4];
            }
            #pragma unroll
            for (int nf = 0; nf < 8; nf++) {
                uint32_t b[2];
                const uint32_t* pb = Vc + (ks*8 + lc) * VST + nf*8 + lr;
                b[0] = pb[0];
                b[1] = pb[4*VST];
                mma_tf32(o[0][nf], a[0], b);
                mma_tf32(o[1][nf], a[1], b);
            }
        }
        __syncthreads();   // all reads of buf t&1 done before t+1 prefetch hits it
    }

    // Epilogue: normalize and write [b,s,d]
    #pragma unroll
    for (int mf = 0; mf < 2; mf++) {
        const float inv0 = 1.f / lrow[mf][0], inv1 = 1.f / lrow[mf][1];
        const int s0 = q0 + base + mf*16 + lr, s1 = s0 + 8;
        float* d0 = g_attn + ((size_t)bI * SSEQ + s0) * DD + h * DHH + 2*lc;
        float* d1 = g_attn + ((size_t)bI * SSEQ + s1) * DD + h * DHH + 2*lc;
        #pragma unroll
        for (int nf = 0; nf < 8; nf++) {
            float2 w0, w1;
            w0.x = o[mf][nf][0] * inv0; w0.y = o[mf][nf][1] * inv0;
            w1.x = o[mf][nf][2] * inv1; w1.y = o[mf][nf][3] * inv1;
            *(float2*)(d0 + nf*8) = w0;
            *(float2*)(d1 + nf*8) = w1;
        }
    }
}

// ---------------------------------------------------------------------------
extern "C" void kernel_launch(void* const* d_in, const int* in_sizes, int n_in,
                              void* d_out, int out_size) {
    const float* x    = (const float*)d_in[0];
    const int*   mask = (const int*)  d_in[1];
    const float* Wqkv = (const float*)d_in[2];
    const float* bqkv = (const float*)d_in[3];
    const float* Wo   = (const float*)d_in[4];
    const float* bo   = (const float*)d_in[5];
    float* out = (float*)d_out;

    const int attn_smem = (512*QST + 2*64*KST + 2*64*VST) * (int)sizeof(uint32_t);
    cudaFuncSetAttribute(attn_mma, cudaFuncAttributeMaxDynamicSharedMemorySize,
                         attn_smem);

    compact_one<<<1, 1024>>>(mask);
    qkv_mma<<<dim3(E3/128, (BB*SSEQ)/128), 256>>>(x, Wqkv, bqkv);
    attn_mma<<<dim3(BB*HH, SSEQ/256), 256, attn_smem>>>();
    out_mma<<<dim3(DD/128, (BB*SSEQ)/128), 256>>>(Wo, bo, out);
}